// round 13
// baseline (speedup 1.0000x reference)
#include <cuda_runtime.h>

#define NH 128
#define MAXG 16384
#define MAXP 524288

typedef unsigned long long ull;

// ---------------- scratch (no allocations allowed) ----------------
__device__ __align__(16) float g_S[MAXG * NH];   // per-grid raw segment means
__device__ __align__(16) float g_U[MAXG * NH];   // per-grid u vectors
__device__ float g_C[MAXG];                      // per-grid scalar offset
__device__ int   g_off[MAXG + 1];                // exclusive prefix of grid_sizes
__device__ int   g_seg[MAXP];                    // seg id per pos sample
__device__ float g_B1[NH * NH];                  // Wk @ Wi
__device__ float g_kb[NH];                       // Wk @ bi
__device__ float g_q[NH];                        // bi^T Wk
__device__ __align__(16) float g_M[NH * NH];     // A row-major: g_M[d*NH+k] = A[d][k]
__device__ __align__(16) float g_v[NH];          // Wi^T Wk bi
__device__ __align__(16) float g_w[NH];          // Wi^T Wk^T bi
__device__ float g_c0;                           // bi^T Wk bi + bk

// ------- stage 0a + scan fused: blocks 0..NH-1 = B1 rows (+kb),
//         block NH = q, block NH+1 = exclusive scan of grid_sizes ----
__global__ void __launch_bounds__(128) prep_kernel(
        const float* __restrict__ Wi,
        const float* __restrict__ Wk,
        const float* __restrict__ bi,
        const int* __restrict__ sizes, int G) {
    __shared__ int wsum[4];
    int b = blockIdx.x;
    int t = threadIdx.x;
    if (b < NH) {
        int d = b;
        float acc = 0.f;
        #pragma unroll 4
        for (int e = 0; e < NH; e++)
            acc += __ldg(&Wk[d * NH + e]) * __ldg(&Wi[e * NH + t]);
        g_B1[d * NH + t] = acc;
        if (t == 0) {
            float a2 = 0.f;
            for (int e = 0; e < NH; e++) a2 += Wk[d * NH + e] * bi[e];
            g_kb[d] = a2;
        }
    } else if (b == NH) {
        int e = t;
        float acc = 0.f;
        #pragma unroll 4
        for (int d = 0; d < NH; d++)
            acc += __ldg(&bi[d]) * __ldg(&Wk[d * NH + e]);
        g_q[e] = acc;
    } else {
        // two-pass exclusive scan with 128 threads
        int lane = t & 31, wid = t >> 5;
        int per = (G + 127) >> 7;
        int base = t * per;
        int s = 0;
        for (int i = 0; i < per; i++)
            if (base + i < G) s += __ldg(&sizes[base + i]);
        int iv = s;
        #pragma unroll
        for (int o = 1; o < 32; o <<= 1) {
            int tt = __shfl_up_sync(0xFFFFFFFFu, iv, o);
            if (lane >= o) iv += tt;
        }
        if (lane == 31) wsum[wid] = iv;
        __syncthreads();
        int woff = 0;
        #pragma unroll
        for (int ww = 0; ww < 4; ww++) if (ww < wid) woff += wsum[ww];
        int run = iv - s + woff;
        for (int i = 0; i < per; i++) {
            if (base + i < G) {
                g_off[base + i] = run;
                run += __ldg(&sizes[base + i]);
            }
        }
        if (base < G && base + per >= G) g_off[G] = run;
    }
}

// ---------------- stage 0b: A (row-major into g_M), v, w, c0 -------
__global__ void small2_kernel(const float* __restrict__ Wi,
                              const float* __restrict__ bi,
                              const float* __restrict__ bk) {
    int b = blockIdx.x;
    int t = threadIdx.x;
    if (b < NH) {
        int k = b;
        float acc = 0.f;
        #pragma unroll 4
        for (int d = 0; d < NH; d++)
            acc += __ldg(&Wi[d * NH + k]) * g_B1[d * NH + t];
        g_M[k * NH + t] = acc;   // A row-major: A[k][t]
        if (t == 0) {
            float vv = 0.f;
            for (int d = 0; d < NH; d++) vv += Wi[d * NH + k] * g_kb[d];
            g_v[k] = vv;
        }
    } else {
        float acc = 0.f;
        #pragma unroll 4
        for (int e = 0; e < NH; e++)
            acc += g_q[e] * __ldg(&Wi[e * NH + t]);
        g_w[t] = acc;
        if (t == 0) {
            float c = bk[0];
            for (int e = 0; e < NH; e++) c += g_q[e] * bi[e];
            g_c0 = c;
        }
    }
}

// ---------------- stage 2: segment mean (+ C[g] = w.s + c0) --------
// 128 threads (4 warps). Indices staged in smem; each warp issues 4
// independent full-row LDG.128s per batch (rows w, w+4, w+8, w+12).
__global__ void __launch_bounds__(128) segmean_kernel(
        const float* __restrict__ emb_,
        const int* __restrict__ pos) {
    __shared__ int sidx[128];
    __shared__ float4 red[4][32];
    int g = blockIdx.x;
    int tid = threadIdx.x;
    int lane = tid & 31, w = tid >> 5;
    int s0 = g_off[g], s1 = g_off[g + 1];
    int cnt = s1 - s0;

    float4 acc = make_float4(0.f, 0.f, 0.f, 0.f);
    for (int base = s0; base < s1; base += 128) {
        int m = s1 - base; if (m > 128) m = 128;
        if (tid < m) sidx[tid] = __ldg(&pos[base + tid]);
        __syncthreads();
        int r = w;
        while (r + 12 < m) {
            int i0 = sidx[r], i1 = sidx[r + 4], i2 = sidx[r + 8], i3 = sidx[r + 12];
            float4 a0 = __ldg((const float4*)(emb_ + (size_t)i0 * NH) + lane);
            float4 a1 = __ldg((const float4*)(emb_ + (size_t)i1 * NH) + lane);
            float4 a2 = __ldg((const float4*)(emb_ + (size_t)i2 * NH) + lane);
            float4 a3 = __ldg((const float4*)(emb_ + (size_t)i3 * NH) + lane);
            acc.x += a0.x + a1.x + a2.x + a3.x;
            acc.y += a0.y + a1.y + a2.y + a3.y;
            acc.z += a0.z + a1.z + a2.z + a3.z;
            acc.w += a0.w + a1.w + a2.w + a3.w;
            r += 16;
        }
        for (; r < m; r += 4) {
            int i = sidx[r];
            float4 a = __ldg((const float4*)(emb_ + (size_t)i * NH) + lane);
            acc.x += a.x; acc.y += a.y; acc.z += a.z; acc.w += a.w;
        }
        __syncthreads();
    }
    red[w][lane] = acc;
    __syncthreads();

    if (tid < 32) {
        float4 v = red[0][tid];
        #pragma unroll
        for (int ww = 1; ww < 4; ww++) {
            float4 a = red[ww][tid];
            v.x += a.x; v.y += a.y; v.z += a.z; v.w += a.w;
        }
        float inv = (cnt > 0) ? (1.f / (float)cnt) : 0.f;
        v.x *= inv; v.y *= inv; v.z *= inv; v.w *= inv;
        ((float4*)(g_S + (size_t)g * NH))[tid] = v;
        // C[g] = w . s + c0 (folded here; s chunk is in v)
        float4 wv = __ldg((const float4*)g_w + tid);
        float part = v.x * wv.x + v.y * wv.y + v.z * wv.z + v.w * wv.w;
        #pragma unroll
        for (int o = 16; o; o >>= 1) part += __shfl_down_sync(0xFFFFFFFFu, part, o);
        if (tid == 0) g_C[g] = part + g_c0;
    }
    for (int p = s0 + tid; p < s1; p += 128) g_seg[p] = g;
}

// ---------------- stage 3: U = A @ s + v, M in regs, FFMA2 ---------
// 128 threads: thread d holds A[d][:] as 64 f32x2 registers. Packed
// fma.rn.f32x2 halves the FMA instruction stream; s read from smem as
// 64-bit broadcasts (no pack movs). Persistent blocks, TG grids/tile.
#define TG 8
#define UCB 444   // 3 CTAs/SM * 148
__global__ void __launch_bounds__(128) ucvec_kernel(int G) {
    __shared__ float sS[TG * NH];
    int d = threadIdx.x;

    ull Mr[64];
    {
        const ull* mrow = (const ull*)(g_M + (size_t)d * NH);
        #pragma unroll
        for (int j = 0; j < 64; j++) Mr[j] = __ldg(mrow + j);
    }
    float vd = g_v[d];

    for (int t0 = blockIdx.x * TG; t0 < G; t0 += UCB * TG) {
        int ng = G - t0; if (ng > TG) ng = TG;
        __syncthreads();
        for (int i = d; i < ng * 32; i += 128)
            ((float4*)sS)[i] = ((const float4*)g_S)[(size_t)t0 * 32 + i];
        __syncthreads();

        ull acc2[TG];
        #pragma unroll
        for (int i = 0; i < TG; i++) acc2[i] = 0ull;

        const ull* s64 = (const ull*)sS;
        #pragma unroll 8
        for (int k4 = 0; k4 < 32; k4++) {
            ull m0 = Mr[2 * k4], m1 = Mr[2 * k4 + 1];
            #pragma unroll
            for (int i = 0; i < TG; i++) {
                ull s0 = s64[i * 64 + 2 * k4];       // LDS.64 broadcast
                ull s1 = s64[i * 64 + 2 * k4 + 1];
                asm("fma.rn.f32x2 %0, %1, %2, %0;" : "+l"(acc2[i]) : "l"(m0), "l"(s0));
                asm("fma.rn.f32x2 %0, %1, %2, %0;" : "+l"(acc2[i]) : "l"(m1), "l"(s1));
            }
        }
        #pragma unroll
        for (int i = 0; i < TG; i++) {
            if (i < ng) {
                float lo, hi;
                asm("mov.b64 {%0, %1}, %2;" : "=f"(lo), "=f"(hi) : "l"(acc2[i]));
                g_U[(size_t)(t0 + i) * NH + d] = lo + hi + vd;
            }
        }
    }
}

// ---------------- stage 4: logits (4 samples per warp) -------------
// 8 lanes per sample; each lane does 4 independent float4 loads per table
// (8 outstanding LDG.128 per lane). 3 shuffles per warp reduce all 4 samples.
__global__ void __launch_bounds__(256) logits_kernel(
        const float* __restrict__ emb,
        const int* __restrict__ pos,
        const int* __restrict__ neg,
        float* __restrict__ out,
        int P, int total, int ratio) {
    int t = blockIdx.x * blockDim.x + threadIdx.x;
    int warp = t >> 5;
    int lane = threadIdx.x & 31;
    int sl = lane & 7;                 // lane within sample group
    int sm = warp * 4 + (lane >> 3);   // sample id
    int smc = (sm < total) ? sm : (total - 1);

    int idx, g;
    if (smc < P) {
        idx = __ldg(&pos[smc]);
        g = g_seg[smc];
    } else {
        int m = smc - P;
        idx = __ldg(&neg[m]);
        g = g_seg[m / ratio];
    }

    const float4* x = (const float4*)(emb + (size_t)idx * NH);
    const float4* u = (const float4*)(g_U + (size_t)g * NH);

    float4 a0 = __ldg(&x[sl]);
    float4 a1 = __ldg(&x[sl + 8]);
    float4 a2 = __ldg(&x[sl + 16]);
    float4 a3 = __ldg(&x[sl + 24]);
    float4 b0 = __ldg(&u[sl]);
    float4 b1 = __ldg(&u[sl + 8]);
    float4 b2 = __ldg(&u[sl + 16]);
    float4 b3 = __ldg(&u[sl + 24]);

    float acc = a0.x * b0.x + a0.y * b0.y + a0.z * b0.z + a0.w * b0.w;
    acc += a1.x * b1.x + a1.y * b1.y + a1.z * b1.z + a1.w * b1.w;
    acc += a2.x * b2.x + a2.y * b2.y + a2.z * b2.z + a2.w * b2.w;
    acc += a3.x * b3.x + a3.y * b3.y + a3.z * b3.z + a3.w * b3.w;

    acc += __shfl_down_sync(0xFFFFFFFFu, acc, 4);
    acc += __shfl_down_sync(0xFFFFFFFFu, acc, 2);
    acc += __shfl_down_sync(0xFFFFFFFFu, acc, 1);

    if (sl == 0 && sm < total) out[sm] = acc + g_C[g];
}

// ---------------- launch ----------------
extern "C" void kernel_launch(void* const* d_in, const int* in_sizes, int n_in,
                              void* d_out, int out_size) {
    const float* embedding  = (const float*)d_in[0];
    const float* embedding_ = (const float*)d_in[1];
    const int*   grid_sizes = (const int*)d_in[2];
    const int*   pos        = (const int*)d_in[3];
    const int*   neg        = (const int*)d_in[4];
    const float* Wi         = (const float*)d_in[5];
    const float* bi         = (const float*)d_in[6];
    const float* Wk         = (const float*)d_in[7];
    const float* bk         = (const float*)d_in[8];
    float* out = (float*)d_out;

    int G  = in_sizes[2];
    int P  = in_sizes[3];
    int PN = in_sizes[4];
    int ratio = PN / P;
    int total = P + PN;

    prep_kernel<<<NH + 2, 128>>>(Wi, Wk, bi, grid_sizes, G);
    small2_kernel<<<NH + 1, NH>>>(Wi, bi, bk);
    segmean_kernel<<<G, 128>>>(embedding_, pos);
    ucvec_kernel<<<UCB, 128>>>(G);
    // 4 samples per warp, 8 warps per block -> 32 samples per block
    logits_kernel<<<(total + 31) / 32, 256>>>(embedding, pos, neg, out, P, total, ratio);
}

// round 14
// speedup vs baseline: 1.0766x; 1.0766x over previous
#include <cuda_runtime.h>

#define NH 128
#define MAXG 16384
#define MAXP 524288

// ---------------- scratch (no allocations allowed) ----------------
__device__ __align__(16) float g_S[MAXG * NH];   // per-grid raw segment means
__device__ __align__(16) float g_U[MAXG * NH];   // per-grid u vectors
__device__ float g_C[MAXG];                      // per-grid scalar offset
__device__ int   g_off[MAXG + 1];                // exclusive prefix of grid_sizes
__device__ int   g_seg[MAXP];                    // seg id per pos sample
__device__ float g_B1[NH * NH];                  // Wk @ Wi
__device__ float g_kb[NH];                       // Wk @ bi
__device__ float g_q[NH];                        // bi^T Wk
__device__ __align__(16) float g_M[NH * NH];     // A row-major: g_M[d*NH+k] = A[d][k]
__device__ __align__(16) float g_v[NH];          // Wi^T Wk bi
__device__ __align__(16) float g_w[NH];          // Wi^T Wk^T bi
__device__ float g_c0;                           // bi^T Wk bi + bk

// ------- stage 0a + scan fused: blocks 0..NH-1 = B1 rows (+kb),
//         block NH = q, block NH+1 = exclusive scan of grid_sizes ----
__global__ void __launch_bounds__(128) prep_kernel(
        const float* __restrict__ Wi,
        const float* __restrict__ Wk,
        const float* __restrict__ bi,
        const int* __restrict__ sizes, int G) {
    __shared__ int wsum[4];
    int b = blockIdx.x;
    int t = threadIdx.x;
    if (b < NH) {
        int d = b;
        float acc = 0.f;
        #pragma unroll 4
        for (int e = 0; e < NH; e++)
            acc += __ldg(&Wk[d * NH + e]) * __ldg(&Wi[e * NH + t]);
        g_B1[d * NH + t] = acc;
        if (t == 0) {
            float a2 = 0.f;
            for (int e = 0; e < NH; e++) a2 += Wk[d * NH + e] * bi[e];
            g_kb[d] = a2;
        }
    } else if (b == NH) {
        int e = t;
        float acc = 0.f;
        #pragma unroll 4
        for (int d = 0; d < NH; d++)
            acc += __ldg(&bi[d]) * __ldg(&Wk[d * NH + e]);
        g_q[e] = acc;
    } else {
        // two-pass exclusive scan with 128 threads
        int lane = t & 31, wid = t >> 5;
        int per = (G + 127) >> 7;
        int base = t * per;
        int s = 0;
        for (int i = 0; i < per; i++)
            if (base + i < G) s += __ldg(&sizes[base + i]);
        int iv = s;
        #pragma unroll
        for (int o = 1; o < 32; o <<= 1) {
            int tt = __shfl_up_sync(0xFFFFFFFFu, iv, o);
            if (lane >= o) iv += tt;
        }
        if (lane == 31) wsum[wid] = iv;
        __syncthreads();
        int woff = 0;
        #pragma unroll
        for (int ww = 0; ww < 4; ww++) if (ww < wid) woff += wsum[ww];
        int run = iv - s + woff;
        for (int i = 0; i < per; i++) {
            if (base + i < G) {
                g_off[base + i] = run;
                run += __ldg(&sizes[base + i]);
            }
        }
        if (base < G && base + per >= G) g_off[G] = run;
    }
}

// ---------------- stage 0b: A (row-major into g_M), v, w, c0 -------
__global__ void small2_kernel(const float* __restrict__ Wi,
                              const float* __restrict__ bi,
                              const float* __restrict__ bk) {
    int b = blockIdx.x;
    int t = threadIdx.x;
    if (b < NH) {
        int k = b;
        float acc = 0.f;
        #pragma unroll 4
        for (int d = 0; d < NH; d++)
            acc += __ldg(&Wi[d * NH + k]) * g_B1[d * NH + t];
        g_M[k * NH + t] = acc;   // A row-major: A[k][t]
        if (t == 0) {
            float vv = 0.f;
            for (int d = 0; d < NH; d++) vv += Wi[d * NH + k] * g_kb[d];
            g_v[k] = vv;
        }
    } else {
        float acc = 0.f;
        #pragma unroll 4
        for (int e = 0; e < NH; e++)
            acc += g_q[e] * __ldg(&Wi[e * NH + t]);
        g_w[t] = acc;
        if (t == 0) {
            float c = bk[0];
            for (int e = 0; e < NH; e++) c += g_q[e] * bi[e];
            g_c0 = c;
        }
    }
}

// ---------------- stage 2: segment mean (+ C[g] = w.s + c0) --------
// 128 threads (4 warps). Indices staged in smem; each warp issues 4
// independent full-row LDG.128s per batch (rows w, w+4, w+8, w+12).
__global__ void __launch_bounds__(128) segmean_kernel(
        const float* __restrict__ emb_,
        const int* __restrict__ pos) {
    __shared__ int sidx[128];
    __shared__ float4 red[4][32];
    int g = blockIdx.x;
    int tid = threadIdx.x;
    int lane = tid & 31, w = tid >> 5;
    int s0 = g_off[g], s1 = g_off[g + 1];
    int cnt = s1 - s0;

    float4 acc = make_float4(0.f, 0.f, 0.f, 0.f);
    for (int base = s0; base < s1; base += 128) {
        int m = s1 - base; if (m > 128) m = 128;
        if (tid < m) sidx[tid] = __ldg(&pos[base + tid]);
        __syncthreads();
        int r = w;
        while (r + 12 < m) {
            int i0 = sidx[r], i1 = sidx[r + 4], i2 = sidx[r + 8], i3 = sidx[r + 12];
            float4 a0 = __ldg((const float4*)(emb_ + (size_t)i0 * NH) + lane);
            float4 a1 = __ldg((const float4*)(emb_ + (size_t)i1 * NH) + lane);
            float4 a2 = __ldg((const float4*)(emb_ + (size_t)i2 * NH) + lane);
            float4 a3 = __ldg((const float4*)(emb_ + (size_t)i3 * NH) + lane);
            acc.x += a0.x + a1.x + a2.x + a3.x;
            acc.y += a0.y + a1.y + a2.y + a3.y;
            acc.z += a0.z + a1.z + a2.z + a3.z;
            acc.w += a0.w + a1.w + a2.w + a3.w;
            r += 16;
        }
        for (; r < m; r += 4) {
            int i = sidx[r];
            float4 a = __ldg((const float4*)(emb_ + (size_t)i * NH) + lane);
            acc.x += a.x; acc.y += a.y; acc.z += a.z; acc.w += a.w;
        }
        __syncthreads();
    }
    red[w][lane] = acc;
    __syncthreads();

    if (tid < 32) {
        float4 v = red[0][tid];
        #pragma unroll
        for (int ww = 1; ww < 4; ww++) {
            float4 a = red[ww][tid];
            v.x += a.x; v.y += a.y; v.z += a.z; v.w += a.w;
        }
        float inv = (cnt > 0) ? (1.f / (float)cnt) : 0.f;
        v.x *= inv; v.y *= inv; v.z *= inv; v.w *= inv;
        ((float4*)(g_S + (size_t)g * NH))[tid] = v;
        // C[g] = w . s + c0 (folded here; s chunk is in v)
        float4 wv = __ldg((const float4*)g_w + tid);
        float part = v.x * wv.x + v.y * wv.y + v.z * wv.z + v.w * wv.w;
        #pragma unroll
        for (int o = 16; o; o >>= 1) part += __shfl_down_sync(0xFFFFFFFFu, part, o);
        if (tid == 0) g_C[g] = part + g_c0;
    }
    for (int p = s0 + tid; p < s1; p += 128) g_seg[p] = g;
}

// ---------------- stage 3: U = A @ s + v, M in REGISTERS (R11) -----
// 128 threads: thread d holds A[d][:] as 32 float4 registers. Persistent
// blocks grid-stride over tiles of TG grids; only the 4KB s-tile is in
// smem (warp-broadcast LDS). 8 independent FMA chains -> FFMA-issue bound.
#define TG 8
#define UCB 444   // 3 CTAs/SM * 148
__global__ void __launch_bounds__(128) ucvec_kernel(int G) {
    __shared__ float sS[TG * NH];
    int d = threadIdx.x;

    float4 Mr[32];
    #pragma unroll
    for (int k4 = 0; k4 < 32; k4++)
        Mr[k4] = __ldg((const float4*)(g_M + (size_t)d * NH) + k4);
    float vd = g_v[d];

    for (int t0 = blockIdx.x * TG; t0 < G; t0 += UCB * TG) {
        int ng = G - t0; if (ng > TG) ng = TG;
        __syncthreads();
        for (int i = d; i < ng * 32; i += 128)
            ((float4*)sS)[i] = ((const float4*)g_S)[(size_t)t0 * 32 + i];
        __syncthreads();
        float acc[TG];
        #pragma unroll
        for (int i = 0; i < TG; i++) acc[i] = vd;
        #pragma unroll
        for (int k4 = 0; k4 < 32; k4++) {
            #pragma unroll
            for (int i = 0; i < TG; i++) {
                float4 sv = ((const float4*)sS)[i * 32 + k4];  // broadcast
                acc[i] += Mr[k4].x * sv.x + Mr[k4].y * sv.y
                        + Mr[k4].z * sv.z + Mr[k4].w * sv.w;
            }
        }
        #pragma unroll
        for (int i = 0; i < TG; i++)
            if (i < ng) g_U[(size_t)(t0 + i) * NH + d] = acc[i];
    }
}

// ---------------- stage 4: logits (8 samples per warp) -------------
// 4 lanes per sample; each lane does 8 independent float4 loads per table
// (16 outstanding LDG.128 per lane). 2 shuffles per warp reduce 8 samples.
__global__ void __launch_bounds__(256) logits_kernel(
        const float* __restrict__ emb,
        const int* __restrict__ pos,
        const int* __restrict__ neg,
        float* __restrict__ out,
        int P, int total, int ratio) {
    int t = blockIdx.x * blockDim.x + threadIdx.x;
    int warp = t >> 5;
    int lane = threadIdx.x & 31;
    int sl = lane & 3;                 // lane within sample group (0-3)
    int sm = warp * 8 + (lane >> 2);   // sample id
    int smc = (sm < total) ? sm : (total - 1);

    int idx, g;
    if (smc < P) {
        idx = __ldg(&pos[smc]);
        g = g_seg[smc];
    } else {
        int m = smc - P;
        idx = __ldg(&neg[m]);
        g = g_seg[m / ratio];
    }

    const float4* x = (const float4*)(emb + (size_t)idx * NH);
    const float4* u = (const float4*)(g_U + (size_t)g * NH);

    float4 a[8], b[8];
    #pragma unroll
    for (int i = 0; i < 8; i++) a[i] = __ldg(&x[sl + 4 * i]);
    #pragma unroll
    for (int i = 0; i < 8; i++) b[i] = __ldg(&u[sl + 4 * i]);

    float acc = 0.f;
    #pragma unroll
    for (int i = 0; i < 8; i++)
        acc += a[i].x * b[i].x + a[i].y * b[i].y + a[i].z * b[i].z + a[i].w * b[i].w;

    acc += __shfl_down_sync(0xFFFFFFFFu, acc, 2);
    acc += __shfl_down_sync(0xFFFFFFFFu, acc, 1);

    if (sl == 0 && sm < total) out[sm] = acc + g_C[g];
}

// ---------------- launch ----------------
extern "C" void kernel_launch(void* const* d_in, const int* in_sizes, int n_in,
                              void* d_out, int out_size) {
    const float* embedding  = (const float*)d_in[0];
    const float* embedding_ = (const float*)d_in[1];
    const int*   grid_sizes = (const int*)d_in[2];
    const int*   pos        = (const int*)d_in[3];
    const int*   neg        = (const int*)d_in[4];
    const float* Wi         = (const float*)d_in[5];
    const float* bi         = (const float*)d_in[6];
    const float* Wk         = (const float*)d_in[7];
    const float* bk         = (const float*)d_in[8];
    float* out = (float*)d_out;

    int G  = in_sizes[2];
    int P  = in_sizes[3];
    int PN = in_sizes[4];
    int ratio = PN / P;
    int total = P + PN;

    prep_kernel<<<NH + 2, 128>>>(Wi, Wk, bi, grid_sizes, G);
    small2_kernel<<<NH + 1, NH>>>(Wi, bi, bk);
    segmean_kernel<<<G, 128>>>(embedding_, pos);
    ucvec_kernel<<<UCB, 128>>>(G);
    // 8 samples per warp, 8 warps per block -> 64 samples per block
    logits_kernel<<<(total + 63) / 64, 256>>>(embedding, pos, neg, out, P, total, ratio);
}

// round 15
// speedup vs baseline: 1.1107x; 1.0316x over previous
#include <cuda_runtime.h>

#define NH 128
#define MAXG 16384
#define MAXP 524288

// ---------------- scratch (no allocations allowed) ----------------
__device__ __align__(16) float g_S[MAXG * NH];   // per-grid raw segment means
__device__ __align__(16) float g_U[MAXG * NH];   // per-grid u vectors
__device__ float g_C[MAXG];                      // per-grid scalar offset
__device__ int   g_off[MAXG + 1];                // exclusive prefix of grid_sizes
__device__ int   g_seg[MAXP];                    // seg id per pos sample
__device__ float g_B1[NH * NH];                  // Wk @ Wi
__device__ float g_kb[NH];                       // Wk @ bi
__device__ float g_q[NH];                        // bi^T Wk
__device__ __align__(16) float g_M[NH * NH];     // A row-major: g_M[d*NH+k] = A[d][k]
__device__ __align__(16) float g_v[NH];          // Wi^T Wk bi
__device__ __align__(16) float g_w[NH];          // Wi^T Wk^T bi
__device__ float g_c0;                           // bi^T Wk bi + bk

// ------- stage 0a + scan fused: blocks 0..NH-1 = B1 rows (+kb),
//         block NH = q, block NH+1 = exclusive scan of grid_sizes ----
__global__ void __launch_bounds__(128) prep_kernel(
        const float* __restrict__ Wi,
        const float* __restrict__ Wk,
        const float* __restrict__ bi,
        const int* __restrict__ sizes, int G) {
    __shared__ int wsum[4];
    int b = blockIdx.x;
    int t = threadIdx.x;
    if (b < NH) {
        int d = b;
        float acc = 0.f;
        #pragma unroll 4
        for (int e = 0; e < NH; e++)
            acc += __ldg(&Wk[d * NH + e]) * __ldg(&Wi[e * NH + t]);
        g_B1[d * NH + t] = acc;
        if (t == 0) {
            float a2 = 0.f;
            for (int e = 0; e < NH; e++) a2 += Wk[d * NH + e] * bi[e];
            g_kb[d] = a2;
        }
    } else if (b == NH) {
        int e = t;
        float acc = 0.f;
        #pragma unroll 4
        for (int d = 0; d < NH; d++)
            acc += __ldg(&bi[d]) * __ldg(&Wk[d * NH + e]);
        g_q[e] = acc;
    } else {
        // two-pass exclusive scan with 128 threads
        int lane = t & 31, wid = t >> 5;
        int per = (G + 127) >> 7;
        int base = t * per;
        int s = 0;
        for (int i = 0; i < per; i++)
            if (base + i < G) s += __ldg(&sizes[base + i]);
        int iv = s;
        #pragma unroll
        for (int o = 1; o < 32; o <<= 1) {
            int tt = __shfl_up_sync(0xFFFFFFFFu, iv, o);
            if (lane >= o) iv += tt;
        }
        if (lane == 31) wsum[wid] = iv;
        __syncthreads();
        int woff = 0;
        #pragma unroll
        for (int ww = 0; ww < 4; ww++) if (ww < wid) woff += wsum[ww];
        int run = iv - s + woff;
        for (int i = 0; i < per; i++) {
            if (base + i < G) {
                g_off[base + i] = run;
                run += __ldg(&sizes[base + i]);
            }
        }
        if (base < G && base + per >= G) g_off[G] = run;
    }
}

// ---------------- stage 0b: A (row-major into g_M), v, w, c0 -------
__global__ void small2_kernel(const float* __restrict__ Wi,
                              const float* __restrict__ bi,
                              const float* __restrict__ bk) {
    int b = blockIdx.x;
    int t = threadIdx.x;
    if (b < NH) {
        int k = b;
        float acc = 0.f;
        #pragma unroll 4
        for (int d = 0; d < NH; d++)
            acc += __ldg(&Wi[d * NH + k]) * g_B1[d * NH + t];
        g_M[k * NH + t] = acc;   // A row-major: A[k][t]
        if (t == 0) {
            float vv = 0.f;
            for (int d = 0; d < NH; d++) vv += Wi[d * NH + k] * g_kb[d];
            g_v[k] = vv;
        }
    } else {
        float acc = 0.f;
        #pragma unroll 4
        for (int e = 0; e < NH; e++)
            acc += g_q[e] * __ldg(&Wi[e * NH + t]);
        g_w[t] = acc;
        if (t == 0) {
            float c = bk[0];
            for (int e = 0; e < NH; e++) c += g_q[e] * bi[e];
            g_c0 = c;
        }
    }
}

// ---------------- stage 2: segment mean (+ C[g] = w.s + c0) --------
// 128 threads (4 warps). Indices staged in smem; each warp issues 4
// independent full-row LDG.128s per batch (rows w, w+4, w+8, w+12).
__global__ void __launch_bounds__(128) segmean_kernel(
        const float* __restrict__ emb_,
        const int* __restrict__ pos) {
    __shared__ int sidx[128];
    __shared__ float4 red[4][32];
    int g = blockIdx.x;
    int tid = threadIdx.x;
    int lane = tid & 31, w = tid >> 5;
    int s0 = g_off[g], s1 = g_off[g + 1];
    int cnt = s1 - s0;

    float4 acc = make_float4(0.f, 0.f, 0.f, 0.f);
    for (int base = s0; base < s1; base += 128) {
        int m = s1 - base; if (m > 128) m = 128;
        if (tid < m) sidx[tid] = __ldg(&pos[base + tid]);
        __syncthreads();
        int r = w;
        while (r + 12 < m) {
            int i0 = sidx[r], i1 = sidx[r + 4], i2 = sidx[r + 8], i3 = sidx[r + 12];
            float4 a0 = __ldg((const float4*)(emb_ + (size_t)i0 * NH) + lane);
            float4 a1 = __ldg((const float4*)(emb_ + (size_t)i1 * NH) + lane);
            float4 a2 = __ldg((const float4*)(emb_ + (size_t)i2 * NH) + lane);
            float4 a3 = __ldg((const float4*)(emb_ + (size_t)i3 * NH) + lane);
            acc.x += a0.x + a1.x + a2.x + a3.x;
            acc.y += a0.y + a1.y + a2.y + a3.y;
            acc.z += a0.z + a1.z + a2.z + a3.z;
            acc.w += a0.w + a1.w + a2.w + a3.w;
            r += 16;
        }
        for (; r < m; r += 4) {
            int i = sidx[r];
            float4 a = __ldg((const float4*)(emb_ + (size_t)i * NH) + lane);
            acc.x += a.x; acc.y += a.y; acc.z += a.z; acc.w += a.w;
        }
        __syncthreads();
    }
    red[w][lane] = acc;
    __syncthreads();

    if (tid < 32) {
        float4 v = red[0][tid];
        #pragma unroll
        for (int ww = 1; ww < 4; ww++) {
            float4 a = red[ww][tid];
            v.x += a.x; v.y += a.y; v.z += a.z; v.w += a.w;
        }
        float inv = (cnt > 0) ? (1.f / (float)cnt) : 0.f;
        v.x *= inv; v.y *= inv; v.z *= inv; v.w *= inv;
        ((float4*)(g_S + (size_t)g * NH))[tid] = v;
        // C[g] = w . s + c0 (folded here; s chunk is in v)
        float4 wv = __ldg((const float4*)g_w + tid);
        float part = v.x * wv.x + v.y * wv.y + v.z * wv.z + v.w * wv.w;
        #pragma unroll
        for (int o = 16; o; o >>= 1) part += __shfl_down_sync(0xFFFFFFFFu, part, o);
        if (tid == 0) g_C[g] = part + g_c0;
    }
    for (int p = s0 + tid; p < s1; p += 128) g_seg[p] = g;
}

// ---------------- stage 3: U = A @ s + v, split-k over 2 halves ----
// 256 threads: thread (d, h) holds A[d][h*64 .. h*64+63] as 16 float4
// registers (~100 regs -> 2 CTAs/SM, 16 warps: better latency cover).
// Halves combine through a 4KB smem buffer. Persistent blocks.
#define TG 8
#define UCB2 296   // 2 CTAs/SM * 148
__global__ void __launch_bounds__(256) ucvec_kernel(int G) {
    __shared__ float sS[TG * NH];
    __shared__ float red[TG][NH];
    int t = threadIdx.x;
    int d = t & 127;
    int h = t >> 7;                    // 0 or 1: which k-half

    float4 Mr[16];
    #pragma unroll
    for (int k4 = 0; k4 < 16; k4++)
        Mr[k4] = __ldg((const float4*)(g_M + (size_t)d * NH) + h * 16 + k4);
    float vd = g_v[d];

    for (int t0 = blockIdx.x * TG; t0 < G; t0 += UCB2 * TG) {
        int ng = G - t0; if (ng > TG) ng = TG;
        __syncthreads();
        for (int i = t; i < ng * 32; i += 256)
            ((float4*)sS)[i] = ((const float4*)g_S)[(size_t)t0 * 32 + i];
        __syncthreads();
        float acc[TG];
        #pragma unroll
        for (int i = 0; i < TG; i++) acc[i] = 0.f;
        #pragma unroll
        for (int k4 = 0; k4 < 16; k4++) {
            #pragma unroll
            for (int i = 0; i < TG; i++) {
                float4 sv = ((const float4*)sS)[i * 32 + h * 16 + k4];  // broadcast
                acc[i] += Mr[k4].x * sv.x + Mr[k4].y * sv.y
                        + Mr[k4].z * sv.z + Mr[k4].w * sv.w;
            }
        }
        if (h == 1) {
            #pragma unroll
            for (int i = 0; i < TG; i++) red[i][d] = acc[i];
        }
        __syncthreads();
        if (h == 0) {
            #pragma unroll
            for (int i = 0; i < TG; i++)
                if (i < ng) g_U[(size_t)(t0 + i) * NH + d] = acc[i] + red[i][d] + vd;
        }
    }
}

// ---------------- stage 4: logits (4 samples per warp, R11) --------
// 8 lanes per sample; each lane does 4 independent float4 loads per table
// (8 outstanding LDG.128 per lane). 3 shuffles per warp reduce all 4 samples.
__global__ void __launch_bounds__(256) logits_kernel(
        const float* __restrict__ emb,
        const int* __restrict__ pos,
        const int* __restrict__ neg,
        float* __restrict__ out,
        int P, int total, int ratio) {
    int t = blockIdx.x * blockDim.x + threadIdx.x;
    int warp = t >> 5;
    int lane = threadIdx.x & 31;
    int sl = lane & 7;                 // lane within sample group
    int sm = warp * 4 + (lane >> 3);   // sample id
    int smc = (sm < total) ? sm : (total - 1);

    int idx, g;
    if (smc < P) {
        idx = __ldg(&pos[smc]);
        g = g_seg[smc];
    } else {
        int m = smc - P;
        idx = __ldg(&neg[m]);
        g = g_seg[m / ratio];
    }

    const float4* x = (const float4*)(emb + (size_t)idx * NH);
    const float4* u = (const float4*)(g_U + (size_t)g * NH);

    float4 a0 = __ldg(&x[sl]);
    float4 a1 = __ldg(&x[sl + 8]);
    float4 a2 = __ldg(&x[sl + 16]);
    float4 a3 = __ldg(&x[sl + 24]);
    float4 b0 = __ldg(&u[sl]);
    float4 b1 = __ldg(&u[sl + 8]);
    float4 b2 = __ldg(&u[sl + 16]);
    float4 b3 = __ldg(&u[sl + 24]);

    float acc = a0.x * b0.x + a0.y * b0.y + a0.z * b0.z + a0.w * b0.w;
    acc += a1.x * b1.x + a1.y * b1.y + a1.z * b1.z + a1.w * b1.w;
    acc += a2.x * b2.x + a2.y * b2.y + a2.z * b2.z + a2.w * b2.w;
    acc += a3.x * b3.x + a3.y * b3.y + a3.z * b3.z + a3.w * b3.w;

    acc += __shfl_down_sync(0xFFFFFFFFu, acc, 4);
    acc += __shfl_down_sync(0xFFFFFFFFu, acc, 2);
    acc += __shfl_down_sync(0xFFFFFFFFu, acc, 1);

    if (sl == 0 && sm < total) out[sm] = acc + g_C[g];
}

// ---------------- launch ----------------
extern "C" void kernel_launch(void* const* d_in, const int* in_sizes, int n_in,
                              void* d_out, int out_size) {
    const float* embedding  = (const float*)d_in[0];
    const float* embedding_ = (const float*)d_in[1];
    const int*   grid_sizes = (const int*)d_in[2];
    const int*   pos        = (const int*)d_in[3];
    const int*   neg        = (const int*)d_in[4];
    const float* Wi         = (const float*)d_in[5];
    const float* bi         = (const float*)d_in[6];
    const float* Wk         = (const float*)d_in[7];
    const float* bk         = (const float*)d_in[8];
    float* out = (float*)d_out;

    int G  = in_sizes[2];
    int P  = in_sizes[3];
    int PN = in_sizes[4];
    int ratio = PN / P;
    int total = P + PN;

    prep_kernel<<<NH + 2, 128>>>(Wi, Wk, bi, grid_sizes, G);
    small2_kernel<<<NH + 1, NH>>>(Wi, bi, bk);
    segmean_kernel<<<G, 128>>>(embedding_, pos);
    ucvec_kernel<<<UCB2, 256>>>(G);
    // 4 samples per warp, 8 warps per block -> 32 samples per block
    logits_kernel<<<(total + 31) / 32, 256>>>(embedding, pos, neg, out, P, total, ratio);
}